// round 16
// baseline (speedup 1.0000x reference)
#include <cuda_runtime.h>
#include <cuda_bf16.h>

// CRF NLL: out = -(sum_b (score_b - partition_b)),  B=512, S=1024, T=32.
//
// Linear-domain forward recurrence with power-of-2 rescaling:
//   alpha_s = D(e_s) M^T alpha_{s-1}, M = exp(trans), tracked as p * 2^off.
// Matvec: lane j publishes p_j via STS, all lanes read back via LDS.128
// broadcast (no syncwarp: same-warp LSU program order, branch-free body),
// computed with PACKED f32x2 FFMA (PTX fma.rn.f32x2; ptxas never emits
// FFMA2 from C++). 4 acc chains x 4 deep, ld.shared.v2.u64 feeds packed
// operands directly. Per-step scale 2^-k from one-step-stale A_0.
// tags buffer is int32 on device (JAX x64-disabled downcast of jnp.int64).

#define BB 512
#define SS 1024
#define TT 32
#define PD 8
#define LN2F 0.6931471805599453f

__device__ float    g_partial[BB];
__device__ unsigned g_ctr = 0;

__device__ __forceinline__ float warp_sum(float v) {
#pragma unroll
    for (int o = 16; o; o >>= 1) v += __shfl_xor_sync(0xFFFFFFFFu, v, o);
    return v;
}

__device__ __forceinline__ void sts_f32(unsigned addr, float v) {
    asm volatile("st.shared.b32 [%0], %1;" :: "r"(addr), "f"(v) : "memory");
}

// 32-wide broadcast dot product in packed f32x2.
__device__ __forceinline__ float matvec32_x2(unsigned sa,
                                             const unsigned long long* Mp) {
    unsigned long long acc0, acc1, acc2, acc3, q0, q1;

    asm volatile("ld.shared.v2.u64 {%0,%1}, [%2];" : "=l"(q0), "=l"(q1) : "r"(sa));
    asm("mul.rn.f32x2 %0, %1, %2;" : "=l"(acc0) : "l"(q0), "l"(Mp[0]));
    asm("mul.rn.f32x2 %0, %1, %2;" : "=l"(acc1) : "l"(q1), "l"(Mp[1]));
    asm volatile("ld.shared.v2.u64 {%0,%1}, [%2];" : "=l"(q0), "=l"(q1) : "r"(sa + 16u));
    asm("mul.rn.f32x2 %0, %1, %2;" : "=l"(acc2) : "l"(q0), "l"(Mp[2]));
    asm("mul.rn.f32x2 %0, %1, %2;" : "=l"(acc3) : "l"(q1), "l"(Mp[3]));
#pragma unroll
    for (int g = 2; g < 8; g++) {
        asm volatile("ld.shared.v2.u64 {%0,%1}, [%2];"
                     : "=l"(q0), "=l"(q1) : "r"(sa + 16u * g));
        asm("fma.rn.f32x2 %0, %1, %2, %3;"
            : "=l"(acc0) : "l"(q0), "l"(Mp[2 * g]), "l"(acc0));
        asm("fma.rn.f32x2 %0, %1, %2, %3;"
            : "=l"(acc1) : "l"(q1), "l"(Mp[2 * g + 1]), "l"(acc1));
        // rotate: next g feeds acc2/acc3
        unsigned long long t;
        t = acc0; acc0 = acc2; acc2 = t;
        t = acc1; acc1 = acc3; acc3 = t;
    }
    unsigned long long s0, s1;
    asm("add.rn.f32x2 %0, %1, %2;" : "=l"(s0) : "l"(acc0), "l"(acc1));
    asm("add.rn.f32x2 %0, %1, %2;" : "=l"(s1) : "l"(acc2), "l"(acc3));
    asm("add.rn.f32x2 %0, %1, %2;" : "=l"(s0) : "l"(s0), "l"(s1));
    float lo, hi;
    asm("mov.b64 {%0, %1}, %2;" : "=f"(lo), "=f"(hi) : "l"(s0));
    return lo + hi;
}

__global__ void __launch_bounds__(128, 1) crf_main(
    const float* __restrict__ em, const int* __restrict__ tags,
    const float* __restrict__ mask, const float* __restrict__ trans,
    const float* __restrict__ startt, const float* __restrict__ endt,
    float* __restrict__ out)
{
    __shared__ __align__(16) float sp[4][2][TT];   // per-warp ping-pong state
    const int w    = threadIdx.x >> 5;
    const int lane = threadIdx.x & 31;
    const int b    = blockIdx.x * 4 + w;           // one warp == one batch
    const size_t embase = (size_t)b * SS * TT;

    const unsigned sbase =
        (unsigned)__cvta_generic_to_shared(&sp[w][0][0]);   // +128 = buffer 1

    // Mp[i] = packed {exp(trans[2i][lane]), exp(trans[2i+1][lane])}
    unsigned long long Mp[16];
#pragma unroll
    for (int i = 0; i < 16; i++) {
        float a = __expf(trans[(2 * i) * TT + lane]);
        float c = __expf(trans[(2 * i + 1) * TT + lane]);
        asm("mov.b64 %0, {%1, %2};" : "=l"(Mp[i]) : "f"(a), "f"(c));
    }

    // Prefetch pipelines (PD steps deep). Step n -> sequence index si = 1+n.
    float em_pf[PD], m_pf[PD];
#pragma unroll
    for (int u = 0; u < PD; u++) {
        em_pf[u] = em[embase + (size_t)(1 + u) * TT + lane];
        m_pf[u]  = mask[b * SS + 1 + u];
    }

    float p  = __expf(startt[lane] + em[embase + lane]);  // alpha0 (linear)
    float ex = __expf(em_pf[0]);
    float av = 1.0f;
    int offset = 0;
    unsigned wb = 0;                                      // ping-pong (0/128)

    // Steps 0..1023; step 1023 (si = 1024) is a dummy with mask forced to 0.
#pragma unroll 1
    for (int n0 = 0; n0 < SS; n0 += PD) {
#pragma unroll
        for (int u = 0; u < PD; u++) {
            const int n = n0 + u;

            // Stale-exponent rescale (pure ALU, off the chain)
            unsigned eb  = (__float_as_uint(av) >> 23) & 0xFFu;
            int      k   = (int)eb - 127;
            float scalef = __uint_as_float((254u - eb) << 23);   // 2^-k
            float emsc   = ex * scalef;
            float m      = m_pf[u];

            // Publish state, then broadcast-read (same-warp LSU order; no sync)
            sts_f32(sbase + wb + lane * 4u, p);

            // Prefetch step n+PD into slot u (si = 1+n+PD; guard the tail)
            {
                int sn = 1 + n + PD;
                bool ok = sn < SS;                        // warp-uniform
                em_pf[u] = ok ? em[embase + (size_t)sn * TT + lane] : 0.f;
                m_pf[u]  = ok ? mask[b * SS + sn] : 0.f;
            }

            // Matvec: A_lane = sum_i p_i * M[i][lane]  (packed f32x2)
            float A = matvec32_x2(sbase + wb, Mp);

            float avn = __shfl_sync(0xFFFFFFFFu, A, 0);  // next step's scale src
            float pn  = A * emsc;
            bool upd  = (m != 0.f);
            p = upd ? pn : p;
            offset += upd ? k : 0;
            av = avn;
            wb ^= 128u;
            ex = __expf(em_pf[(u + 1) & (PD - 1)]);  // next step's exp (off chain)
        }
    }

    // partition_b = ln(sum_j p_j * exp(end_j)) + offset * ln2
    float val = warp_sum(p * __expf(endt[lane]));
    float partition = logf(val) + (float)offset * LN2F;

    // ---- gold-path score, lanes strided over sequence positions ----
    float sc = 0.f, ms = 0.f;
    const int* tg = tags + (size_t)b * SS;
#pragma unroll 4
    for (int it = 0; it < SS / 32; it++) {
        int s  = it * 32 + lane;
        int tc = tg[s];
        float mm = mask[b * SS + s];
        ms += mm;
        if (s == 0) {
            sc += startt[tc] + em[embase + tc];
        } else {
            int tp = tg[s - 1];
            sc += (em[embase + (size_t)s * TT + tc] + trans[tp * TT + tc]) * mm;
        }
    }
    sc = warp_sum(sc); ms = warp_sum(ms);

    if (lane == 0) {
        int last = (int)ms - 1;
        g_partial[b] = (sc + endt[tg[last]]) - partition;
        __threadfence();
    }
    __syncthreads();

    // ---- last-CTA-done final reduction (no separate kernel) ----
    if (w == 0) {
        unsigned done = 0;
        if (lane == 0) done = atomicAdd(&g_ctr, 1);
        done = __shfl_sync(0xFFFFFFFFu, done, 0);
        if (done == gridDim.x - 1) {
            __threadfence();
            float v = 0.f;
#pragma unroll
            for (int i = 0; i < BB / 32; i++) v += g_partial[lane + i * 32];
            v = warp_sum(v);
            if (lane == 0) { out[0] = -v; g_ctr = 0; }   // reset for graph replay
        }
    }
}

extern "C" void kernel_launch(void* const* d_in, const int* in_sizes, int n_in,
                              void* d_out, int out_size) {
    const float* em    = (const float*)d_in[0];
    const int*   tags  = (const int*)d_in[1];
    const float* mask  = (const float*)d_in[2];
    const float* trans = (const float*)d_in[3];
    const float* st    = (const float*)d_in[4];
    const float* en    = (const float*)d_in[5];
    (void)in_sizes; (void)n_in; (void)out_size;

    crf_main<<<BB / 4, 128>>>(em, tags, mask, trans, st, en, (float*)d_out);
}